// round 6
// baseline (speedup 1.0000x reference)
#include <cuda_runtime.h>
#include <cuda_bf16.h>
#include <cstdint>

#define BATCH   4
#define SEQL    4096
#define DMODEL  2048
#define HALF    32
#define N2      64
#define MTOT    (BATCH*SEQL)
#define CHUNK   64
#define NCHUNK  (SEQL/CHUNK)

// ---------------- scratch ----------------
__device__ __nv_bfloat16 g_W1h[N2 * DMODEL];   // [j][d]  B operand of GEMM1
__device__ __nv_bfloat16 g_W1l[N2 * DMODEL];
__device__ __nv_bfloat16 g_W2h[DMODEL * N2];   // [d][j]  B operand of GEMM2
__device__ __nv_bfloat16 g_W2l[DMODEL * N2];
__device__ float g_Bu[MTOT * N2];
__device__ float g_carry[BATCH * NCHUNK * N2];
__device__ float g_pref [BATCH * NCHUNK * N2];
__device__ float g_par[192];

// ---------------- helpers ----------------
__device__ __forceinline__ void cvt_hl(float x, uint16_t& h, uint16_t& l) {
    __nv_bfloat16 hb = __float2bfloat16_rn(x);
    float r = x - __bfloat162float(hb);
    __nv_bfloat16 lb = __float2bfloat16_rn(r);
    h = *(uint16_t*)&hb;
    l = *(uint16_t*)&lb;
}

__device__ __forceinline__ void cvt8(const float4& v0, const float4& v1,
                                     uint4& h, uint4& l) {
    uint16_t hh[8], ll[8];
    cvt_hl(v0.x, hh[0], ll[0]); cvt_hl(v0.y, hh[1], ll[1]);
    cvt_hl(v0.z, hh[2], ll[2]); cvt_hl(v0.w, hh[3], ll[3]);
    cvt_hl(v1.x, hh[4], ll[4]); cvt_hl(v1.y, hh[5], ll[5]);
    cvt_hl(v1.z, hh[6], ll[6]); cvt_hl(v1.w, hh[7], ll[7]);
    h = make_uint4((uint32_t)hh[0] | ((uint32_t)hh[1] << 16),
                   (uint32_t)hh[2] | ((uint32_t)hh[3] << 16),
                   (uint32_t)hh[4] | ((uint32_t)hh[5] << 16),
                   (uint32_t)hh[6] | ((uint32_t)hh[7] << 16));
    l = make_uint4((uint32_t)ll[0] | ((uint32_t)ll[1] << 16),
                   (uint32_t)ll[2] | ((uint32_t)ll[3] << 16),
                   (uint32_t)ll[4] | ((uint32_t)ll[5] << 16),
                   (uint32_t)ll[6] | ((uint32_t)ll[7] << 16));
}

__device__ __forceinline__ void mma16816(float* c, const uint32_t* a,
                                         const uint32_t* b) {
    asm volatile(
        "mma.sync.aligned.m16n8k16.row.col.f32.bf16.bf16.f32 "
        "{%0,%1,%2,%3}, {%4,%5,%6,%7}, {%8,%9}, {%0,%1,%2,%3};"
        : "+f"(c[0]), "+f"(c[1]), "+f"(c[2]), "+f"(c[3])
        : "r"(a[0]), "r"(a[1]), "r"(a[2]), "r"(a[3]), "r"(b[0]), "r"(b[1]));
}

// Panels: kp in [0,8) holds 8 k-values; entry = 16B per row; XOR(row,kp) swizzle.
// 64-row panels for both A and B: 1024 B/panel, 8 KB per operand half.
#define PANEL 1024

__device__ __forceinline__ void ldA16(const char* base, int p, int rb, int g,
                                      int tig, uint32_t* a) {
    const char* q0 = base + p * PANEL;
    const char* q1 = base + (p + 1) * PANEL;
    int x0 = p & 7, x1 = (p + 1) & 7;
    a[0] = *(const uint32_t*)(q0 + ((rb + g)     ^ x0) * 16 + tig * 4);
    a[1] = *(const uint32_t*)(q0 + ((rb + g + 8) ^ x0) * 16 + tig * 4);
    a[2] = *(const uint32_t*)(q1 + ((rb + g)     ^ x1) * 16 + tig * 4);
    a[3] = *(const uint32_t*)(q1 + ((rb + g + 8) ^ x1) * 16 + tig * 4);
}
__device__ __forceinline__ void ldB8(const char* base, int p, int nb, int g,
                                     int tig, uint32_t* b) {
    b[0] = *(const uint32_t*)(base + p * PANEL
                              + ((nb + g) ^ (p & 7)) * 16 + tig * 4);
    b[1] = *(const uint32_t*)(base + (p + 1) * PANEL
                              + ((nb + g) ^ ((p + 1) & 7)) * 16 + tig * 4);
}

// ---------------- setup: per-state parameters ----------------
__global__ void k_params(const float* __restrict__ Lur,
                         const float* __restrict__ Lim,
                         const float* __restrict__ logD) {
    int n = threadIdx.x;
    if (n >= HALF) return;
    float x   = Lur[n];
    float sp  = (x > 20.f) ? x : log1pf(expf(x));
    float lre = -(sp + 1e-4f + 0.01f);
    float lim = Lim[n];
    float dt  = expf(logD[n]);
    float ar = lre * dt, ai = lim * dt;
    float er = expf(ar);
    float lbr = er * cosf(ai);
    float lbi = er * sinf(ai);
    float den = lre * lre + lim * lim;
    float nr = lbr - 1.f, ni = lbi;
    float sre = (nr * lre + ni * lim) / den;
    float sim = (ni * lre - nr * lim) / den;
    float er64 = expf((float)CHUNK * ar);
    float a64  = (float)CHUNK * ai;
    float lbSr = er64 * cosf(a64);
    float lbSi = er64 * sinf(a64);
    g_par[n]       = lbr;  g_par[32 + n]  = lbi;
    g_par[64 + n]  = lbSr; g_par[96 + n]  = lbSi;
    g_par[128 + n] = sre;  g_par[160 + n] = sim;
}

__global__ void k_w1(const float* __restrict__ Bre, const float* __restrict__ Bim) {
    for (int idx = blockIdx.x * blockDim.x + threadIdx.x; idx < N2 * DMODEL;
         idx += gridDim.x * blockDim.x) {
        int j = idx >> 11;
        int d = idx & 2047;
        int n = j & 31;
        float sre = g_par[128 + n], sim = g_par[160 + n];
        float br = Bre[n * DMODEL + d], bi = Bim[n * DMODEL + d];
        float v = (j < 32) ? (sre * br - sim * bi) : (sre * bi + sim * br);
        uint16_t h, l;
        cvt_hl(v, h, l);
        g_W1h[idx] = *(__nv_bfloat16*)&h;
        g_W1l[idx] = *(__nv_bfloat16*)&l;
    }
}

__global__ void k_w2(const float* __restrict__ Cre, const float* __restrict__ Cim) {
    for (int idx = blockIdx.x * blockDim.x + threadIdx.x; idx < DMODEL * N2;
         idx += gridDim.x * blockDim.x) {
        int d = idx >> 6;
        int j = idx & 63;
        float v = (j < 32) ? (2.f * Cre[d * HALF + j])
                           : (-2.f * Cim[d * HALF + (j - 32)]);
        uint16_t h, l;
        cvt_hl(v, h, l);
        g_W2h[idx] = *(__nv_bfloat16*)&h;
        g_W2l[idx] = *(__nv_bfloat16*)&l;
    }
}

// ---------------- GEMM1: Bu[16384,64] = u @ W1^T  (bf16x3 HMMA) ----------------
// 256 thr, BM=64, BN=64, K_TILE=64; grid 256; 2 blocks/SM; warp = m16 x n32.
__global__ __launch_bounds__(256, 2) void k_gemm1(const float* __restrict__ u) {
    __shared__ __align__(16) char smem[32768];
    char* pAh = smem;
    char* pAl = smem + 8192;
    char* pBh = smem + 16384;
    char* pBl = smem + 24576;
    int tid = threadIdx.x;
    int lane = tid & 31, g = lane >> 2, tig = lane & 3;
    int w = tid >> 5, wm = w >> 1, wn = w & 1;   // wm 0..3, wn 0..1
    int m0 = blockIdx.x * 64;

    float acc[4][4];
    #pragma unroll
    for (int nt = 0; nt < 4; ++nt)
        #pragma unroll
        for (int i = 0; i < 4; ++i) acc[nt][i] = 0.f;

    float4 ru[2][2];
    uint4 rwh[2], rwl[2];

    // prefetch tile 0: A 64 rows x 64 k (512 tasks), B 64 n x 64 k (512 tasks)
    #pragma unroll
    for (int i = 0; i < 2; ++i) {
        int task = tid + 256 * i;
        int row = task >> 3, kp = task & 7;
        const float* s = u + (size_t)(m0 + row) * DMODEL + kp * 8;
        ru[i][0] = *(const float4*)s;
        ru[i][1] = *(const float4*)(s + 4);
    }
    #pragma unroll
    for (int i = 0; i < 2; ++i) {
        int task = tid + 256 * i;
        int n = task >> 3, kp = task & 7;
        size_t off = ((size_t)n * DMODEL + kp * 8) * 2;
        rwh[i] = *(const uint4*)((const char*)g_W1h + off);
        rwl[i] = *(const uint4*)((const char*)g_W1l + off);
    }

    for (int kt = 0; kt < DMODEL / 64; ++kt) {
        __syncthreads();
        #pragma unroll
        for (int i = 0; i < 2; ++i) {
            int task = tid + 256 * i;
            int row = task >> 3, kp = task & 7;
            uint4 h, l;
            cvt8(ru[i][0], ru[i][1], h, l);
            int off = kp * PANEL + (row ^ kp) * 16;
            *(uint4*)(pAh + off) = h;
            *(uint4*)(pAl + off) = l;
        }
        #pragma unroll
        for (int i = 0; i < 2; ++i) {
            int task = tid + 256 * i;
            int n = task >> 3, kp = task & 7;
            int off = kp * PANEL + (n ^ kp) * 16;
            *(uint4*)(pBh + off) = rwh[i];
            *(uint4*)(pBl + off) = rwl[i];
        }
        __syncthreads();
        if (kt + 1 < DMODEL / 64) {
            int kb = (kt + 1) * 64;
            #pragma unroll
            for (int i = 0; i < 2; ++i) {
                int task = tid + 256 * i;
                int row = task >> 3, kp = task & 7;
                const float* s = u + (size_t)(m0 + row) * DMODEL + kb + kp * 8;
                ru[i][0] = *(const float4*)s;
                ru[i][1] = *(const float4*)(s + 4);
            }
            #pragma unroll
            for (int i = 0; i < 2; ++i) {
                int task = tid + 256 * i;
                int n = task >> 3, kp = task & 7;
                size_t off = ((size_t)n * DMODEL + kb + kp * 8) * 2;
                rwh[i] = *(const uint4*)((const char*)g_W1h + off);
                rwl[i] = *(const uint4*)((const char*)g_W1l + off);
            }
        }
        #pragma unroll
        for (int ks = 0; ks < 4; ++ks) {
            int p = ks * 2;
            uint32_t ah[4], al[4];
            ldA16(pAh, p, wm * 16, g, tig, ah);
            ldA16(pAl, p, wm * 16, g, tig, al);
            #pragma unroll
            for (int nt = 0; nt < 4; ++nt) {
                int nb = wn * 32 + nt * 8;
                uint32_t bh[2], bl[2];
                ldB8(pBh, p, nb, g, tig, bh);
                ldB8(pBl, p, nb, g, tig, bl);
                mma16816(acc[nt], ah, bh);
                mma16816(acc[nt], ah, bl);
                mma16816(acc[nt], al, bh);
            }
        }
    }
    // epilogue -> g_Bu
    int r0 = m0 + wm * 16 + g;
    #pragma unroll
    for (int nt = 0; nt < 4; ++nt) {
        int col = wn * 32 + nt * 8 + 2 * tig;
        float* a = acc[nt];
        *(float2*)(g_Bu + (size_t)r0 * N2 + col)       = make_float2(a[0], a[1]);
        *(float2*)(g_Bu + (size_t)(r0 + 8) * N2 + col) = make_float2(a[2], a[3]);
    }
}

// ---------------- scan (fp32, unchanged) ----------------
__global__ void k_scan_local() {
    int w = (blockIdx.x * blockDim.x + threadIdx.x) >> 5;
    int lane = threadIdx.x & 31;
    int b = w >> 6, c = w & (NCHUNK - 1);
    float lbr = g_par[lane], lbi = g_par[32 + lane];
    float xr = 0.f, xi = 0.f;
    size_t base = ((size_t)b * SEQL + (size_t)c * CHUNK) * N2;
    for (int i = 0; i < CHUNK; ++i) {
        size_t off = base + (size_t)i * N2;
        float br = g_Bu[off + lane];
        float bi = g_Bu[off + 32 + lane];
        float nr = fmaf(lbr, xr, fmaf(-lbi, xi, br));
        float ni = fmaf(lbr, xi, fmaf( lbi, xr, bi));
        g_Bu[off + lane]      = nr;
        g_Bu[off + 32 + lane] = ni;
        xr = nr; xi = ni;
    }
    int co = (b * NCHUNK + c) * N2;
    g_carry[co + lane] = xr;
    g_carry[co + 32 + lane] = xi;
}

__global__ void k_scan_prefix() {
    int w = threadIdx.x >> 5;
    int lane = threadIdx.x & 31;
    float lbSr = g_par[64 + lane], lbSi = g_par[96 + lane];
    float Pr = 0.f, Pi = 0.f;
    for (int c = 0; c < NCHUNK; ++c) {
        int o = (w * NCHUNK + c) * N2;
        g_pref[o + lane] = Pr;
        g_pref[o + 32 + lane] = Pi;
        float cr = g_carry[o + lane];
        float ci = g_carry[o + 32 + lane];
        float nr = fmaf(lbSr, Pr, fmaf(-lbSi, Pi, cr));
        float ni = fmaf(lbSr, Pi, fmaf( lbSi, Pr, ci));
        Pr = nr; Pi = ni;
    }
}

__global__ void k_scan_fix() {
    int w = (blockIdx.x * blockDim.x + threadIdx.x) >> 5;
    int lane = threadIdx.x & 31;
    int b = w >> 6, c = w & (NCHUNK - 1);
    float lbr = g_par[lane], lbi = g_par[32 + lane];
    int po = (b * NCHUNK + c) * N2;
    float Pr = g_pref[po + lane], Pi = g_pref[po + 32 + lane];
    float pr = lbr, pi = lbi;
    size_t base = ((size_t)b * SEQL + (size_t)c * CHUNK) * N2;
    for (int i = 0; i < CHUNK; ++i) {
        size_t off = base + (size_t)i * N2;
        float ar = pr * Pr - pi * Pi;
        float ai = pr * Pi + pi * Pr;
        g_Bu[off + lane]      += ar;
        g_Bu[off + 32 + lane] += ai;
        float npr = pr * lbr - pi * lbi;
        float npi = pr * lbi + pi * lbr;
        pr = npr; pi = npi;
    }
}

// ---------------- GEMM2: y = X @ W2 + D.u  (bf16x3 HMMA) ----------------
// 256 thr, BM=64, BN=64, K=64 single tile; grid (32, 256); 2 blocks/SM.
__global__ __launch_bounds__(256, 2) void k_gemm2(const float* __restrict__ u,
                                                  const float* __restrict__ Dv,
                                                  float* __restrict__ y) {
    __shared__ __align__(16) char smem[32768];
    char* pAh = smem;
    char* pAl = smem + 8192;
    char* pBh = smem + 16384;
    char* pBl = smem + 24576;
    int tid = threadIdx.x;
    int lane = tid & 31, g = lane >> 2, tig = lane & 3;
    int w = tid >> 5, wm = w >> 1, wn = w & 1;
    int n0 = blockIdx.x * 64;
    int m0 = blockIdx.y * 64;

    // stage A = X (fp32 -> bf16 hi/lo)
    #pragma unroll
    for (int i = 0; i < 2; ++i) {
        int task = tid + 256 * i;
        int row = task >> 3, kp = task & 7;
        const float* s = g_Bu + (size_t)(m0 + row) * N2 + kp * 8;
        uint4 h, l;
        cvt8(*(const float4*)s, *(const float4*)(s + 4), h, l);
        int off = kp * PANEL + (row ^ kp) * 16;
        *(uint4*)(pAh + off) = h;
        *(uint4*)(pAl + off) = l;
    }
    // stage B = W2 rows n0..n0+63
    #pragma unroll
    for (int i = 0; i < 2; ++i) {
        int task = tid + 256 * i;
        int n = task >> 3, kp = task & 7;
        size_t goff = ((size_t)(n0 + n) * N2 + kp * 8) * 2;
        int off = kp * PANEL + (n ^ kp) * 16;
        *(uint4*)(pBh + off) = *(const uint4*)((const char*)g_W2h + goff);
        *(uint4*)(pBl + off) = *(const uint4*)((const char*)g_W2l + goff);
    }
    __syncthreads();

    float acc[4][4];
    #pragma unroll
    for (int nt = 0; nt < 4; ++nt)
        #pragma unroll
        for (int i = 0; i < 4; ++i) acc[nt][i] = 0.f;

    #pragma unroll
    for (int ks = 0; ks < 4; ++ks) {
        int p = ks * 2;
        uint32_t ah[4], al[4];
        ldA16(pAh, p, wm * 16, g, tig, ah);
        ldA16(pAl, p, wm * 16, g, tig, al);
        #pragma unroll
        for (int nt = 0; nt < 4; ++nt) {
            int nb = wn * 32 + nt * 8;
            uint32_t bh[2], bl[2];
            ldB8(pBh, p, nb, g, tig, bh);
            ldB8(pBl, p, nb, g, tig, bl);
            mma16816(acc[nt], ah, bh);
            mma16816(acc[nt], ah, bl);
            mma16816(acc[nt], al, bh);
        }
    }

    // epilogue: y = acc + D*u
    int r0 = m0 + wm * 16 + g;
    #pragma unroll
    for (int nt = 0; nt < 4; ++nt) {
        int col = n0 + wn * 32 + nt * 8 + 2 * tig;
        float2 dv = *(const float2*)(Dv + col);
        float* a = acc[nt];
        size_t o0 = (size_t)r0 * DMODEL + col;
        size_t o1 = o0 + (size_t)8 * DMODEL;
        float2 u0 = *(const float2*)(u + o0);
        float2 u1 = *(const float2*)(u + o1);
        *(float2*)(y + o0) = make_float2(a[0] + dv.x * u0.x, a[1] + dv.y * u0.y);
        *(float2*)(y + o1) = make_float2(a[2] + dv.x * u1.x, a[3] + dv.y * u1.y);
    }
}

// ---------------- launch ----------------
extern "C" void kernel_launch(void* const* d_in, const int* in_sizes, int n_in,
                              void* d_out, int out_size) {
    const float* u    = (const float*)d_in[0];
    const float* Lur  = (const float*)d_in[1];
    const float* Lim  = (const float*)d_in[2];
    const float* Bre  = (const float*)d_in[3];
    const float* Bim  = (const float*)d_in[4];
    const float* Cre  = (const float*)d_in[5];
    const float* Cim  = (const float*)d_in[6];
    const float* Dv   = (const float*)d_in[7];
    const float* logD = (const float*)d_in[8];
    float* y = (float*)d_out;

    k_params<<<1, 32>>>(Lur, Lim, logD);
    k_w1<<<128, 256>>>(Bre, Bim);
    k_w2<<<128, 256>>>(Cre, Cim);
    k_gemm1<<<MTOT / 64, 256>>>(u);
    k_scan_local<<<(BATCH * NCHUNK) / 4, 128>>>();
    k_scan_prefix<<<1, BATCH * 32>>>();
    k_scan_fix<<<(BATCH * NCHUNK) / 4, 128>>>();
    k_gemm2<<<dim3(DMODEL / 64, MTOT / 64), 256>>>(u, Dv, y);
}

// round 7
// speedup vs baseline: 1.1431x; 1.1431x over previous
#include <cuda_runtime.h>
#include <cuda_bf16.h>
#include <cstdint>

#define BATCH   4
#define SEQL    4096
#define DMODEL  2048
#define HALF    32
#define N2      64
#define MTOT    (BATCH*SEQL)
#define CHUNK   64
#define NCHUNK  (SEQL/CHUNK)

// ---------------- scratch ----------------
__device__ __nv_bfloat16 g_W1h[N2 * DMODEL];   // [j][d]  B operand of GEMM1
__device__ __nv_bfloat16 g_W1l[N2 * DMODEL];
__device__ __nv_bfloat16 g_W2h[DMODEL * N2];   // [d][j]  B operand of GEMM2
__device__ __nv_bfloat16 g_W2l[DMODEL * N2];
__device__ float g_Bu[MTOT * N2];
__device__ float g_carry[BATCH * NCHUNK * N2];
__device__ float g_pref [BATCH * NCHUNK * N2];
__device__ float g_par[192];

// ---------------- helpers ----------------
__device__ __forceinline__ uint32_t smem_u32(const void* p) {
    uint32_t a;
    asm("{ .reg .u64 t; cvta.to.shared.u64 t, %1; cvt.u32.u64 %0, t; }"
        : "=r"(a) : "l"(p));
    return a;
}

__device__ __forceinline__ void cvt_hl(float x, uint16_t& h, uint16_t& l) {
    __nv_bfloat16 hb = __float2bfloat16_rn(x);
    float r = x - __bfloat162float(hb);
    __nv_bfloat16 lb = __float2bfloat16_rn(r);
    h = *(uint16_t*)&hb;
    l = *(uint16_t*)&lb;
}

__device__ __forceinline__ void cvt8(const float4& v0, const float4& v1,
                                     uint4& h, uint4& l) {
    uint16_t hh[8], ll[8];
    cvt_hl(v0.x, hh[0], ll[0]); cvt_hl(v0.y, hh[1], ll[1]);
    cvt_hl(v0.z, hh[2], ll[2]); cvt_hl(v0.w, hh[3], ll[3]);
    cvt_hl(v1.x, hh[4], ll[4]); cvt_hl(v1.y, hh[5], ll[5]);
    cvt_hl(v1.z, hh[6], ll[6]); cvt_hl(v1.w, hh[7], ll[7]);
    h = make_uint4((uint32_t)hh[0] | ((uint32_t)hh[1] << 16),
                   (uint32_t)hh[2] | ((uint32_t)hh[3] << 16),
                   (uint32_t)hh[4] | ((uint32_t)hh[5] << 16),
                   (uint32_t)hh[6] | ((uint32_t)hh[7] << 16));
    l = make_uint4((uint32_t)ll[0] | ((uint32_t)ll[1] << 16),
                   (uint32_t)ll[2] | ((uint32_t)ll[3] << 16),
                   (uint32_t)ll[4] | ((uint32_t)ll[5] << 16),
                   (uint32_t)ll[6] | ((uint32_t)ll[7] << 16));
}

__device__ __forceinline__ void mma16816(float* c, const uint32_t* a,
                                         const uint32_t* b) {
    asm volatile(
        "mma.sync.aligned.m16n8k16.row.col.f32.bf16.bf16.f32 "
        "{%0,%1,%2,%3}, {%4,%5,%6,%7}, {%8,%9}, {%0,%1,%2,%3};"
        : "+f"(c[0]), "+f"(c[1]), "+f"(c[2]), "+f"(c[3])
        : "r"(a[0]), "r"(a[1]), "r"(a[2]), "r"(a[3]), "r"(b[0]), "r"(b[1]));
}

__device__ __forceinline__ void ldsm4(uint32_t addr, uint32_t* r) {
    asm volatile(
        "ldmatrix.sync.aligned.m8n8.x4.shared.b16 {%0,%1,%2,%3}, [%4];"
        : "=r"(r[0]), "=r"(r[1]), "=r"(r[2]), "=r"(r[3]) : "r"(addr));
}

// Panels: kp holds 8 k-values; 16B per row; XOR(row, kp) swizzle.
// ldmatrix x4 address: lanes 0-15 -> panel p rows rb+0..15, lanes 16-31 -> panel p+1.
__device__ __forceinline__ uint32_t lmaddr(const char* base, int p, int rb,
                                           int lane, int psz) {
    int pp = p + (lane >> 4);
    int row = rb + (lane & 15);
    return smem_u32(base + pp * psz + (((row ^ (pp & 7)) << 4)));
}

// ---------------- setup ----------------
__global__ void k_params(const float* __restrict__ Lur,
                         const float* __restrict__ Lim,
                         const float* __restrict__ logD) {
    int n = threadIdx.x;
    if (n >= HALF) return;
    float x   = Lur[n];
    float sp  = (x > 20.f) ? x : log1pf(expf(x));
    float lre = -(sp + 1e-4f + 0.01f);
    float lim = Lim[n];
    float dt  = expf(logD[n]);
    float ar = lre * dt, ai = lim * dt;
    float er = expf(ar);
    float lbr = er * cosf(ai);
    float lbi = er * sinf(ai);
    float den = lre * lre + lim * lim;
    float nr = lbr - 1.f, ni = lbi;
    float sre = (nr * lre + ni * lim) / den;
    float sim = (ni * lre - nr * lim) / den;
    float er64 = expf((float)CHUNK * ar);
    float a64  = (float)CHUNK * ai;
    float lbSr = er64 * cosf(a64);
    float lbSi = er64 * sinf(a64);
    g_par[n]       = lbr;  g_par[32 + n]  = lbi;
    g_par[64 + n]  = lbSr; g_par[96 + n]  = lbSi;
    g_par[128 + n] = sre;  g_par[160 + n] = sim;
}

__global__ void k_w1(const float* __restrict__ Bre, const float* __restrict__ Bim) {
    for (int idx = blockIdx.x * blockDim.x + threadIdx.x; idx < N2 * DMODEL;
         idx += gridDim.x * blockDim.x) {
        int j = idx >> 11;
        int d = idx & 2047;
        int n = j & 31;
        float sre = g_par[128 + n], sim = g_par[160 + n];
        float br = Bre[n * DMODEL + d], bi = Bim[n * DMODEL + d];
        float v = (j < 32) ? (sre * br - sim * bi) : (sre * bi + sim * br);
        uint16_t h, l;
        cvt_hl(v, h, l);
        g_W1h[idx] = *(__nv_bfloat16*)&h;
        g_W1l[idx] = *(__nv_bfloat16*)&l;
    }
}

__global__ void k_w2(const float* __restrict__ Cre, const float* __restrict__ Cim) {
    for (int idx = blockIdx.x * blockDim.x + threadIdx.x; idx < DMODEL * N2;
         idx += gridDim.x * blockDim.x) {
        int d = idx >> 6;
        int j = idx & 63;
        float v = (j < 32) ? (2.f * Cre[d * HALF + j])
                           : (-2.f * Cim[d * HALF + (j - 32)]);
        uint16_t h, l;
        cvt_hl(v, h, l);
        g_W2h[idx] = *(__nv_bfloat16*)&h;
        g_W2l[idx] = *(__nv_bfloat16*)&l;
    }
}

// ---------------- GEMM1: Bu = u @ W1^T  (bf16x3 HMMA, LDSM, 2-stage) ----------------
// 256 thr, BM=128, BN=64, K_TILE=64 (8 panels), grid 128; warp = m32 x n32.
// Stage layout: Ah 16K | Al 16K | Bh 8K | Bl 8K  (48 KB), two stages (96 KB dyn).
#define G1_STAGE 49152
__global__ __launch_bounds__(256) void k_gemm1(const float* __restrict__ u) {
    extern __shared__ char smem[];
    int tid = threadIdx.x;
    int lane = tid & 31, g = lane >> 2, tig = lane & 3;
    int w = tid >> 5, wm = w >> 1, wn = w & 1;   // wm 0..3 (m32), wn 0..1 (n32)
    int m0 = blockIdx.x * 128;

    float acc[2][4][4];
    #pragma unroll
    for (int mt = 0; mt < 2; ++mt)
        #pragma unroll
        for (int f = 0; f < 4; ++f)
            #pragma unroll
            for (int i = 0; i < 4; ++i) acc[mt][f][i] = 0.f;

    float4 ru[4][2];
    uint4 rwh[2], rwl[2];

    // LDG tile kb into registers
    #define G1_LDG(kb)                                                        \
        _Pragma("unroll")                                                     \
        for (int i = 0; i < 4; ++i) {                                         \
            int task = tid + 256 * i;                                         \
            int row = task >> 3, kp = task & 7;                               \
            const float* s = u + (size_t)(m0 + row) * DMODEL + (kb) + kp * 8; \
            ru[i][0] = *(const float4*)s;                                     \
            ru[i][1] = *(const float4*)(s + 4);                               \
        }                                                                     \
        _Pragma("unroll")                                                     \
        for (int i = 0; i < 2; ++i) {                                         \
            int task = tid + 256 * i;                                         \
            int n = task >> 3, kp = task & 7;                                 \
            size_t off = ((size_t)n * DMODEL + (kb) + kp * 8) * 2;            \
            rwh[i] = *(const uint4*)((const char*)g_W1h + off);               \
            rwl[i] = *(const uint4*)((const char*)g_W1l + off);               \
        }

    // STS registers into stage s
    #define G1_STS(sbase)                                                     \
        _Pragma("unroll")                                                     \
        for (int i = 0; i < 4; ++i) {                                         \
            int task = tid + 256 * i;                                         \
            int row = task >> 3, kp = task & 7;                               \
            uint4 h, l;                                                       \
            cvt8(ru[i][0], ru[i][1], h, l);                                   \
            int off = kp * 2048 + ((row ^ kp) << 4);                          \
            *(uint4*)((sbase) + off) = h;                                     \
            *(uint4*)((sbase) + 16384 + off) = l;                             \
        }                                                                     \
        _Pragma("unroll")                                                     \
        for (int i = 0; i < 2; ++i) {                                         \
            int task = tid + 256 * i;                                         \
            int n = task >> 3, kp = task & 7;                                 \
            int off = kp * 1024 + ((n ^ kp) << 4);                            \
            *(uint4*)((sbase) + 32768 + off) = rwh[i];                        \
            *(uint4*)((sbase) + 40960 + off) = rwl[i];                        \
        }

    // prologue: tile0 -> stage0; LDG tile1
    G1_LDG(0);
    G1_STS(smem);
    G1_LDG(64);
    __syncthreads();

    for (int kt = 0; kt < DMODEL / 64; ++kt) {
        if (kt + 1 < DMODEL / 64) {
            char* nst = smem + ((kt + 1) & 1) * G1_STAGE;
            G1_STS(nst);
        }
        if (kt + 2 < DMODEL / 64) {
            G1_LDG((kt + 2) * 64);
        }
        char* cur = smem + (kt & 1) * G1_STAGE;
        char* cAh = cur;
        char* cAl = cur + 16384;
        char* cBh = cur + 32768;
        char* cBl = cur + 40960;
        #pragma unroll
        for (int ks = 0; ks < 4; ++ks) {
            int p = ks * 2;
            uint32_t ah0[4], ah1[4], al0[4], al1[4];
            ldsm4(lmaddr(cAh, p, wm * 32,      lane, 2048), ah0);
            ldsm4(lmaddr(cAh, p, wm * 32 + 16, lane, 2048), ah1);
            ldsm4(lmaddr(cAl, p, wm * 32,      lane, 2048), al0);
            ldsm4(lmaddr(cAl, p, wm * 32 + 16, lane, 2048), al1);
            uint32_t bh[8], bl[8];
            ldsm4(lmaddr(cBh, p, wn * 32,      lane, 1024), bh);
            ldsm4(lmaddr(cBh, p, wn * 32 + 16, lane, 1024), bh + 4);
            ldsm4(lmaddr(cBl, p, wn * 32,      lane, 1024), bl);
            ldsm4(lmaddr(cBl, p, wn * 32 + 16, lane, 1024), bl + 4);
            #pragma unroll
            for (int f = 0; f < 4; ++f) {
                // n8 frag f: regs {base+which, base+which+2} of x4 group f>>1
                int q = (f >> 1) * 4 + (f & 1);
                uint32_t bfh[2] = { bh[q], bh[q + 2] };
                uint32_t bfl[2] = { bl[q], bl[q + 2] };
                mma16816(acc[0][f], ah0, bfh);
                mma16816(acc[0][f], ah0, bfl);
                mma16816(acc[0][f], al0, bfh);
                mma16816(acc[1][f], ah1, bfh);
                mma16816(acc[1][f], ah1, bfl);
                mma16816(acc[1][f], al1, bfh);
            }
        }
        __syncthreads();
    }
    // epilogue -> g_Bu
    #pragma unroll
    for (int mt = 0; mt < 2; ++mt) {
        int r0 = m0 + wm * 32 + mt * 16 + g;
        #pragma unroll
        for (int f = 0; f < 4; ++f) {
            int col = wn * 32 + f * 8 + 2 * tig;
            float* a = acc[mt][f];
            *(float2*)(g_Bu + (size_t)r0 * N2 + col)       = make_float2(a[0], a[1]);
            *(float2*)(g_Bu + (size_t)(r0 + 8) * N2 + col) = make_float2(a[2], a[3]);
        }
    }
    #undef G1_LDG
    #undef G1_STS
}

// ---------------- scan (fp32, unchanged) ----------------
__global__ void k_scan_local() {
    int w = (blockIdx.x * blockDim.x + threadIdx.x) >> 5;
    int lane = threadIdx.x & 31;
    int b = w >> 6, c = w & (NCHUNK - 1);
    float lbr = g_par[lane], lbi = g_par[32 + lane];
    float xr = 0.f, xi = 0.f;
    size_t base = ((size_t)b * SEQL + (size_t)c * CHUNK) * N2;
    for (int i = 0; i < CHUNK; ++i) {
        size_t off = base + (size_t)i * N2;
        float br = g_Bu[off + lane];
        float bi = g_Bu[off + 32 + lane];
        float nr = fmaf(lbr, xr, fmaf(-lbi, xi, br));
        float ni = fmaf(lbr, xi, fmaf( lbi, xr, bi));
        g_Bu[off + lane]      = nr;
        g_Bu[off + 32 + lane] = ni;
        xr = nr; xi = ni;
    }
    int co = (b * NCHUNK + c) * N2;
    g_carry[co + lane] = xr;
    g_carry[co + 32 + lane] = xi;
}

__global__ void k_scan_prefix() {
    int w = threadIdx.x >> 5;
    int lane = threadIdx.x & 31;
    float lbSr = g_par[64 + lane], lbSi = g_par[96 + lane];
    float Pr = 0.f, Pi = 0.f;
    for (int c = 0; c < NCHUNK; ++c) {
        int o = (w * NCHUNK + c) * N2;
        g_pref[o + lane] = Pr;
        g_pref[o + 32 + lane] = Pi;
        float cr = g_carry[o + lane];
        float ci = g_carry[o + 32 + lane];
        float nr = fmaf(lbSr, Pr, fmaf(-lbSi, Pi, cr));
        float ni = fmaf(lbSr, Pi, fmaf( lbSi, Pr, ci));
        Pr = nr; Pi = ni;
    }
}

__global__ void k_scan_fix() {
    int w = (blockIdx.x * blockDim.x + threadIdx.x) >> 5;
    int lane = threadIdx.x & 31;
    int b = w >> 6, c = w & (NCHUNK - 1);
    float lbr = g_par[lane], lbi = g_par[32 + lane];
    int po = (b * NCHUNK + c) * N2;
    float Pr = g_pref[po + lane], Pi = g_pref[po + 32 + lane];
    float pr = lbr, pi = lbi;
    size_t base = ((size_t)b * SEQL + (size_t)c * CHUNK) * N2;
    for (int i = 0; i < CHUNK; ++i) {
        size_t off = base + (size_t)i * N2;
        float ar = pr * Pr - pi * Pi;
        float ai = pr * Pi + pi * Pr;
        g_Bu[off + lane]      += ar;
        g_Bu[off + 32 + lane] += ai;
        float npr = pr * lbr - pi * lbi;
        float npi = pr * lbi + pi * lbr;
        pr = npr; pi = npi;
    }
}

// ---------------- GEMM2: y = X @ W2 + D.u  (bf16x3 HMMA, LDSM) ----------------
// 256 thr, BM=128, BN=64, K=64 single tile; grid (32, 128); warp = m32 x n32.
// Smem: Ah 16K | Al 16K | Bh 8K | Bl 8K = 48 KB dynamic.
__global__ __launch_bounds__(256) void k_gemm2(const float* __restrict__ u,
                                               const float* __restrict__ Dv,
                                               float* __restrict__ y) {
    extern __shared__ char smem[];
    char* pAh = smem;
    char* pAl = smem + 16384;
    char* pBh = smem + 32768;
    char* pBl = smem + 40960;
    int tid = threadIdx.x;
    int lane = tid & 31, g = lane >> 2, tig = lane & 3;
    int w = tid >> 5, wm = w >> 1, wn = w & 1;
    int n0 = blockIdx.x * 64;
    int m0 = blockIdx.y * 128;

    // stage A = X (fp32 -> bf16 hi/lo): 128 rows x 8 panels
    #pragma unroll
    for (int i = 0; i < 4; ++i) {
        int task = tid + 256 * i;
        int row = task >> 3, kp = task & 7;
        const float* s = g_Bu + (size_t)(m0 + row) * N2 + kp * 8;
        uint4 h, l;
        cvt8(*(const float4*)s, *(const float4*)(s + 4), h, l);
        int off = kp * 2048 + ((row ^ kp) << 4);
        *(uint4*)(pAh + off) = h;
        *(uint4*)(pAl + off) = l;
    }
    // stage B = W2 rows n0..n0+63
    #pragma unroll
    for (int i = 0; i < 2; ++i) {
        int task = tid + 256 * i;
        int n = task >> 3, kp = task & 7;
        size_t goff = ((size_t)(n0 + n) * N2 + kp * 8) * 2;
        int off = kp * 1024 + ((n ^ kp) << 4);
        *(uint4*)(pBh + off) = *(const uint4*)((const char*)g_W2h + goff);
        *(uint4*)(pBl + off) = *(const uint4*)((const char*)g_W2l + goff);
    }
    __syncthreads();

    float acc[2][4][4];
    #pragma unroll
    for (int mt = 0; mt < 2; ++mt)
        #pragma unroll
        for (int f = 0; f < 4; ++f)
            #pragma unroll
            for (int i = 0; i < 4; ++i) acc[mt][f][i] = 0.f;

    #pragma unroll
    for (int ks = 0; ks < 4; ++ks) {
        int p = ks * 2;
        uint32_t ah0[4], ah1[4], al0[4], al1[4];
        ldsm4(lmaddr(pAh, p, wm * 32,      lane, 2048), ah0);
        ldsm4(lmaddr(pAh, p, wm * 32 + 16, lane, 2048), ah1);
        ldsm4(lmaddr(pAl, p, wm * 32,      lane, 2048), al0);
        ldsm4(lmaddr(pAl, p, wm * 32 + 16, lane, 2048), al1);
        uint32_t bh[8], bl[8];
        ldsm4(lmaddr(pBh, p, wn * 32,      lane, 1024), bh);
        ldsm4(lmaddr(pBh, p, wn * 32 + 16, lane, 1024), bh + 4);
        ldsm4(lmaddr(pBl, p, wn * 32,      lane, 1024), bl);
        ldsm4(lmaddr(pBl, p, wn * 32 + 16, lane, 1024), bl + 4);
        #pragma unroll
        for (int f = 0; f < 4; ++f) {
            int q = (f >> 1) * 4 + (f & 1);
            uint32_t bfh[2] = { bh[q], bh[q + 2] };
            uint32_t bfl[2] = { bl[q], bl[q + 2] };
            mma16816(acc[0][f], ah0, bfh);
            mma16816(acc[0][f], ah0, bfl);
            mma16816(acc[0][f], al0, bfh);
            mma16816(acc[1][f], ah1, bfh);
            mma16816(acc[1][f], ah1, bfl);
            mma16816(acc[1][f], al1, bfh);
        }
    }

    // epilogue: y = acc + D*u
    #pragma unroll
    for (int f = 0; f < 4; ++f) {
        int col = n0 + wn * 32 + f * 8 + 2 * tig;
        float2 dv = *(const float2*)(Dv + col);
        #pragma unroll
        for (int mt = 0; mt < 2; ++mt) {
            int r0 = m0 + wm * 32 + mt * 16 + g;
            float* a = acc[mt][f];
            size_t o0 = (size_t)r0 * DMODEL + col;
            size_t o1 = o0 + (size_t)8 * DMODEL;
            float2 u0 = *(const float2*)(u + o0);
            float2 u1 = *(const float2*)(u + o1);
            *(float2*)(y + o0) = make_float2(a[0] + dv.x * u0.x, a[1] + dv.y * u0.y);
            *(float2*)(y + o1) = make_float2(a[2] + dv.x * u1.x, a[3] + dv.y * u1.y);
        }
    }
}

// ---------------- launch ----------------
extern "C" void kernel_launch(void* const* d_in, const int* in_sizes, int n_in,
                              void* d_out, int out_size) {
    const float* u    = (const float*)d_in[0];
    const float* Lur  = (const float*)d_in[1];
    const float* Lim  = (const float*)d_in[2];
    const float* Bre  = (const float*)d_in[3];
    const float* Bim  = (const float*)d_in[4];
    const float* Cre  = (const float*)d_in[5];
    const float* Cim  = (const float*)d_in[6];
    const float* Dv   = (const float*)d_in[7];
    const float* logD = (const float*)d_in[8];
    float* y = (float*)d_out;

    const int g1_bytes = 2 * G1_STAGE;   // 98304
    const int g2_bytes = 49152;
    cudaFuncSetAttribute(k_gemm1, cudaFuncAttributeMaxDynamicSharedMemorySize,
                         g1_bytes);
    cudaFuncSetAttribute(k_gemm2, cudaFuncAttributeMaxDynamicSharedMemorySize,
                         g2_bytes);

    k_params<<<1, 32>>>(Lur, Lim, logD);
    k_w1<<<128, 256>>>(Bre, Bim);
    k_w2<<<128, 256>>>(Cre, Cim);
    k_gemm1<<<MTOT / 128, 256, g1_bytes>>>(u);
    k_scan_local<<<(BATCH * NCHUNK) / 4, 128>>>();
    k_scan_prefix<<<1, BATCH * 32>>>();
    k_scan_fix<<<(BATCH * NCHUNK) / 4, 128>>>();
    k_gemm2<<<dim3(DMODEL / 64, MTOT / 128), 256, g2_bytes>>>(u, Dv, y);
}

// round 8
// speedup vs baseline: 1.2500x; 1.0935x over previous
#include <cuda_runtime.h>
#include <cuda_bf16.h>
#include <cstdint>

#define BATCH   4
#define SEQL    4096
#define DMODEL  2048
#define HALF    32
#define N2      64
#define MTOT    (BATCH*SEQL)
#define CHUNK   64
#define NCHUNK  (SEQL/CHUNK)

// ---------------- scratch ----------------
__device__ __nv_bfloat16 g_W1h[N2 * DMODEL];   // [j][d]  B operand of GEMM1
__device__ __nv_bfloat16 g_W1l[N2 * DMODEL];
__device__ __nv_bfloat16 g_W2h[DMODEL * N2];   // [d][j]  B operand of GEMM2
__device__ __nv_bfloat16 g_W2l[DMODEL * N2];
__device__ float g_Bu[MTOT * N2];
__device__ __nv_bfloat16 g_Xh[MTOT * N2];      // corrected X, bf16 hi
__device__ __nv_bfloat16 g_Xl[MTOT * N2];      // corrected X, bf16 lo
__device__ float g_carry[BATCH * NCHUNK * N2];
__device__ float g_pref [BATCH * NCHUNK * N2];
__device__ float g_par[192];

// ---------------- helpers ----------------
__device__ __forceinline__ uint32_t smem_u32(const void* p) {
    uint32_t a;
    asm("{ .reg .u64 t; cvta.to.shared.u64 t, %1; cvt.u32.u64 %0, t; }"
        : "=r"(a) : "l"(p));
    return a;
}

__device__ __forceinline__ void cvt_hl(float x, uint16_t& h, uint16_t& l) {
    __nv_bfloat16 hb = __float2bfloat16_rn(x);
    float r = x - __bfloat162float(hb);
    __nv_bfloat16 lb = __float2bfloat16_rn(r);
    h = *(uint16_t*)&hb;
    l = *(uint16_t*)&lb;
}

// paired split: 2 floats -> packed bf16x2 hi + packed bf16x2 lo
__device__ __forceinline__ void cvt_hl2(float x0, float x1,
                                        uint32_t& h, uint32_t& l) {
    uint32_t hp;
    asm("cvt.rn.bf16x2.f32 %0, %1, %2;" : "=r"(hp) : "f"(x1), "f"(x0));
    float f0 = __uint_as_float(hp << 16);
    float f1 = __uint_as_float(hp & 0xffff0000u);
    float r0 = x0 - f0;
    float r1 = x1 - f1;
    asm("cvt.rn.bf16x2.f32 %0, %1, %2;" : "=r"(l) : "f"(r1), "f"(r0));
    h = hp;
}

__device__ __forceinline__ void cvt8(const float4& v0, const float4& v1,
                                     uint4& h, uint4& l) {
    cvt_hl2(v0.x, v0.y, h.x, l.x);
    cvt_hl2(v0.z, v0.w, h.y, l.y);
    cvt_hl2(v1.x, v1.y, h.z, l.z);
    cvt_hl2(v1.z, v1.w, h.w, l.w);
}

__device__ __forceinline__ void mma16816(float* c, const uint32_t* a,
                                         const uint32_t* b) {
    asm volatile(
        "mma.sync.aligned.m16n8k16.row.col.f32.bf16.bf16.f32 "
        "{%0,%1,%2,%3}, {%4,%5,%6,%7}, {%8,%9}, {%0,%1,%2,%3};"
        : "+f"(c[0]), "+f"(c[1]), "+f"(c[2]), "+f"(c[3])
        : "r"(a[0]), "r"(a[1]), "r"(a[2]), "r"(a[3]), "r"(b[0]), "r"(b[1]));
}

__device__ __forceinline__ void ldsm4(uint32_t addr, uint32_t* r) {
    asm volatile(
        "ldmatrix.sync.aligned.m8n8.x4.shared.b16 {%0,%1,%2,%3}, [%4];"
        : "=r"(r[0]), "=r"(r[1]), "=r"(r[2]), "=r"(r[3]) : "r"(addr));
}

// Panels: kp holds 8 k-values; 16B per row; XOR(row, kp) swizzle.
// ldmatrix x4 offset within region: lanes 0-15 -> panel p, 16-31 -> panel p+1.
__device__ __forceinline__ uint32_t lmoff(int p, int rb, int lane, int psz) {
    int pp = p + (lane >> 4);
    int row = rb + (lane & 15);
    return (uint32_t)(pp * psz + (((row ^ (pp & 7)) << 4)));
}

// ---------------- setup ----------------
__global__ void k_params(const float* __restrict__ Lur,
                         const float* __restrict__ Lim,
                         const float* __restrict__ logD) {
    int n = threadIdx.x;
    if (n >= HALF) return;
    float x   = Lur[n];
    float sp  = (x > 20.f) ? x : log1pf(expf(x));
    float lre = -(sp + 1e-4f + 0.01f);
    float lim = Lim[n];
    float dt  = expf(logD[n]);
    float ar = lre * dt, ai = lim * dt;
    float er = expf(ar);
    float lbr = er * cosf(ai);
    float lbi = er * sinf(ai);
    float den = lre * lre + lim * lim;
    float nr = lbr - 1.f, ni = lbi;
    float sre = (nr * lre + ni * lim) / den;
    float sim = (ni * lre - nr * lim) / den;
    float er64 = expf((float)CHUNK * ar);
    float a64  = (float)CHUNK * ai;
    float lbSr = er64 * cosf(a64);
    float lbSi = er64 * sinf(a64);
    g_par[n]       = lbr;  g_par[32 + n]  = lbi;
    g_par[64 + n]  = lbSr; g_par[96 + n]  = lbSi;
    g_par[128 + n] = sre;  g_par[160 + n] = sim;
}

__global__ void k_w1(const float* __restrict__ Bre, const float* __restrict__ Bim) {
    for (int idx = blockIdx.x * blockDim.x + threadIdx.x; idx < N2 * DMODEL;
         idx += gridDim.x * blockDim.x) {
        int j = idx >> 11;
        int d = idx & 2047;
        int n = j & 31;
        float sre = g_par[128 + n], sim = g_par[160 + n];
        float br = Bre[n * DMODEL + d], bi = Bim[n * DMODEL + d];
        float v = (j < 32) ? (sre * br - sim * bi) : (sre * bi + sim * br);
        uint16_t h, l;
        cvt_hl(v, h, l);
        g_W1h[idx] = *(__nv_bfloat16*)&h;
        g_W1l[idx] = *(__nv_bfloat16*)&l;
    }
}

__global__ void k_w2(const float* __restrict__ Cre, const float* __restrict__ Cim) {
    for (int idx = blockIdx.x * blockDim.x + threadIdx.x; idx < DMODEL * N2;
         idx += gridDim.x * blockDim.x) {
        int d = idx >> 6;
        int j = idx & 63;
        float v = (j < 32) ? (2.f * Cre[d * HALF + j])
                           : (-2.f * Cim[d * HALF + (j - 32)]);
        uint16_t h, l;
        cvt_hl(v, h, l);
        g_W2h[idx] = *(__nv_bfloat16*)&h;
        g_W2l[idx] = *(__nv_bfloat16*)&l;
    }
}

// ---------------- GEMM1: Bu = u @ W1^T  (bf16x3 HMMA, LDSM, 2-stage) ----------------
// 256 thr, BM=128, BN=64, K_TILE=64 (8 panels), grid 128; warp = m32 x n32.
// Stage: Ah 16K | Al 16K | Bh 8K | Bl 8K (48 KB), 2 stages.
#define G1_STAGE 49152
__global__ __launch_bounds__(256) void k_gemm1(const float* __restrict__ u) {
    extern __shared__ char smem[];
    int tid = threadIdx.x;
    int lane = tid & 31, g = lane >> 2, tig = lane & 3;
    int w = tid >> 5, wm = w >> 1, wn = w & 1;
    int m0 = blockIdx.x * 128;

    float acc[2][4][4];
    #pragma unroll
    for (int mt = 0; mt < 2; ++mt)
        #pragma unroll
        for (int f = 0; f < 4; ++f)
            #pragma unroll
            for (int i = 0; i < 4; ++i) acc[mt][f][i] = 0.f;

    // hoisted LDSM offsets (within a stage)
    uint32_t oAh0[4], oAh1[4], oAl0[4], oAl1[4];
    uint32_t oBh0[4], oBh1[4], oBl0[4], oBl1[4];
    #pragma unroll
    for (int ks = 0; ks < 4; ++ks) {
        int p = ks * 2;
        oAh0[ks] =         lmoff(p, wm * 32,      lane, 2048);
        oAh1[ks] =         lmoff(p, wm * 32 + 16, lane, 2048);
        oAl0[ks] = 16384 + lmoff(p, wm * 32,      lane, 2048);
        oAl1[ks] = 16384 + lmoff(p, wm * 32 + 16, lane, 2048);
        oBh0[ks] = 32768 + lmoff(p, wn * 32,      lane, 1024);
        oBh1[ks] = 32768 + lmoff(p, wn * 32 + 16, lane, 1024);
        oBl0[ks] = 40960 + lmoff(p, wn * 32,      lane, 1024);
        oBl1[ks] = 40960 + lmoff(p, wn * 32 + 16, lane, 1024);
    }
    uint32_t sb0 = smem_u32(smem);
    uint32_t sb1 = sb0 + G1_STAGE;

    float4 ru[4][2];
    uint4 rwh[2], rwl[2];

    #define G1_LDG(kb)                                                        \
        _Pragma("unroll")                                                     \
        for (int i = 0; i < 4; ++i) {                                         \
            int task = tid + 256 * i;                                         \
            int row = task >> 3, kp = task & 7;                               \
            const float* s = u + (size_t)(m0 + row) * DMODEL + (kb) + kp * 8; \
            ru[i][0] = *(const float4*)s;                                     \
            ru[i][1] = *(const float4*)(s + 4);                               \
        }                                                                     \
        _Pragma("unroll")                                                     \
        for (int i = 0; i < 2; ++i) {                                         \
            int task = tid + 256 * i;                                         \
            int n = task >> 3, kp = task & 7;                                 \
            size_t off = ((size_t)n * DMODEL + (kb) + kp * 8) * 2;            \
            rwh[i] = *(const uint4*)((const char*)g_W1h + off);               \
            rwl[i] = *(const uint4*)((const char*)g_W1l + off);               \
        }

    #define G1_STS(sbase)                                                     \
        _Pragma("unroll")                                                     \
        for (int i = 0; i < 4; ++i) {                                         \
            int task = tid + 256 * i;                                         \
            int row = task >> 3, kp = task & 7;                               \
            uint4 h, l;                                                       \
            cvt8(ru[i][0], ru[i][1], h, l);                                   \
            int off = kp * 2048 + ((row ^ kp) << 4);                          \
            *(uint4*)((sbase) + off) = h;                                     \
            *(uint4*)((sbase) + 16384 + off) = l;                             \
        }                                                                     \
        _Pragma("unroll")                                                     \
        for (int i = 0; i < 2; ++i) {                                         \
            int task = tid + 256 * i;                                         \
            int n = task >> 3, kp = task & 7;                                 \
            int off = kp * 1024 + ((n ^ kp) << 4);                            \
            *(uint4*)((sbase) + 32768 + off) = rwh[i];                        \
            *(uint4*)((sbase) + 40960 + off) = rwl[i];                        \
        }

    G1_LDG(0);
    G1_STS(smem);
    G1_LDG(64);
    __syncthreads();

    for (int kt = 0; kt < DMODEL / 64; ++kt) {
        if (kt + 1 < DMODEL / 64) {
            char* nst = smem + ((kt + 1) & 1) * G1_STAGE;
            G1_STS(nst);
        }
        if (kt + 2 < DMODEL / 64) {
            G1_LDG((kt + 2) * 64);
        }
        uint32_t sb = (kt & 1) ? sb1 : sb0;
        #pragma unroll
        for (int ks = 0; ks < 4; ++ks) {
            uint32_t ah0[4], ah1[4], al0[4], al1[4];
            ldsm4(sb + oAh0[ks], ah0);
            ldsm4(sb + oAh1[ks], ah1);
            ldsm4(sb + oAl0[ks], al0);
            ldsm4(sb + oAl1[ks], al1);
            uint32_t bh[8], bl[8];
            ldsm4(sb + oBh0[ks], bh);
            ldsm4(sb + oBh1[ks], bh + 4);
            ldsm4(sb + oBl0[ks], bl);
            ldsm4(sb + oBl1[ks], bl + 4);
            #pragma unroll
            for (int f = 0; f < 4; ++f) {
                int q = (f >> 1) * 4 + (f & 1);
                uint32_t bfh[2] = { bh[q], bh[q + 2] };
                uint32_t bfl[2] = { bl[q], bl[q + 2] };
                mma16816(acc[0][f], ah0, bfh);
                mma16816(acc[0][f], ah0, bfl);
                mma16816(acc[0][f], al0, bfh);
                mma16816(acc[1][f], ah1, bfh);
                mma16816(acc[1][f], ah1, bfl);
                mma16816(acc[1][f], al1, bfh);
            }
        }
        __syncthreads();
    }
    #pragma unroll
    for (int mt = 0; mt < 2; ++mt) {
        int r0 = m0 + wm * 32 + mt * 16 + g;
        #pragma unroll
        for (int f = 0; f < 4; ++f) {
            int col = wn * 32 + f * 8 + 2 * tig;
            float* a = acc[mt][f];
            *(float2*)(g_Bu + (size_t)r0 * N2 + col)       = make_float2(a[0], a[1]);
            *(float2*)(g_Bu + (size_t)(r0 + 8) * N2 + col) = make_float2(a[2], a[3]);
        }
    }
    #undef G1_LDG
    #undef G1_STS
}

// ---------------- scan phase 1 (prefetched) ----------------
__global__ void k_scan_local() {
    int w = (blockIdx.x * blockDim.x + threadIdx.x) >> 5;
    int lane = threadIdx.x & 31;
    int b = w >> 6, c = w & (NCHUNK - 1);
    float lbr = g_par[lane], lbi = g_par[32 + lane];
    float xr = 0.f, xi = 0.f;
    size_t base = ((size_t)b * SEQL + (size_t)c * CHUNK) * N2;
    float br = g_Bu[base + lane];
    float bi = g_Bu[base + 32 + lane];
    for (int i = 0; i < CHUNK; ++i) {
        size_t off = base + (size_t)i * N2;
        float nbr = 0.f, nbi = 0.f;
        if (i + 1 < CHUNK) {
            nbr = g_Bu[off + N2 + lane];
            nbi = g_Bu[off + N2 + 32 + lane];
        }
        float nr = fmaf(lbr, xr, fmaf(-lbi, xi, br));
        float ni = fmaf(lbr, xi, fmaf( lbi, xr, bi));
        g_Bu[off + lane]      = nr;
        g_Bu[off + 32 + lane] = ni;
        xr = nr; xi = ni;
        br = nbr; bi = nbi;
    }
    int co = (b * NCHUNK + c) * N2;
    g_carry[co + lane] = xr;
    g_carry[co + 32 + lane] = xi;
}

// ---------------- scan phase 2 ----------------
__global__ void k_scan_prefix() {
    int w = threadIdx.x >> 5;
    int lane = threadIdx.x & 31;
    float lbSr = g_par[64 + lane], lbSi = g_par[96 + lane];
    float Pr = 0.f, Pi = 0.f;
    for (int c = 0; c < NCHUNK; ++c) {
        int o = (w * NCHUNK + c) * N2;
        g_pref[o + lane] = Pr;
        g_pref[o + 32 + lane] = Pi;
        float cr = g_carry[o + lane];
        float ci = g_carry[o + 32 + lane];
        float nr = fmaf(lbSr, Pr, fmaf(-lbSi, Pi, cr));
        float ni = fmaf(lbSr, Pi, fmaf( lbSi, Pr, ci));
        Pr = nr; Pi = ni;
    }
}

// ---------------- scan phase 3: fixup + emit bf16 hi/lo X ----------------
__global__ void k_scan_fix() {
    int w = (blockIdx.x * blockDim.x + threadIdx.x) >> 5;
    int lane = threadIdx.x & 31;
    int b = w >> 6, c = w & (NCHUNK - 1);
    float lbr = g_par[lane], lbi = g_par[32 + lane];
    int po = (b * NCHUNK + c) * N2;
    float Pr = g_pref[po + lane], Pi = g_pref[po + 32 + lane];
    float pr = lbr, pi = lbi;
    size_t mbase = (size_t)b * SEQL + (size_t)c * CHUNK;
    size_t base = mbase * N2;
    float br = g_Bu[base + lane];
    float bi = g_Bu[base + 32 + lane];
    for (int i = 0; i < CHUNK; ++i) {
        size_t off = base + (size_t)i * N2;
        float nbr = 0.f, nbi = 0.f;
        if (i + 1 < CHUNK) {
            nbr = g_Bu[off + N2 + lane];
            nbi = g_Bu[off + N2 + 32 + lane];
        }
        float xr = fmaf(pr, Pr, fmaf(-pi, Pi, br));
        float xi = fmaf(pr, Pi, fmaf( pi, Pr, bi));
        uint16_t hr, lr, hi_, li_;
        cvt_hl(xr, hr, lr);
        cvt_hl(xi, hi_, li_);
        size_t ro = (mbase + i) * N2;
        g_Xh[ro + lane]      = *(__nv_bfloat16*)&hr;
        g_Xh[ro + 32 + lane] = *(__nv_bfloat16*)&hi_;
        g_Xl[ro + lane]      = *(__nv_bfloat16*)&lr;
        g_Xl[ro + 32 + lane] = *(__nv_bfloat16*)&li_;
        float npr = pr * lbr - pi * lbi;
        float npi = pr * lbi + pi * lbr;
        pr = npr; pi = npi;
        br = nbr; bi = nbi;
    }
}

// ---------------- GEMM2: y = X @ W2 + D.u  (bf16x3 HMMA, LDSM) ----------------
// 256 thr, BM=128, BN=128, K=64 single tile; grid (16, 128); warp = m32 x n64.
// Smem: Ah 16K | Al 16K | Bh 16K | Bl 16K = 64 KB.
__global__ __launch_bounds__(256) void k_gemm2(const float* __restrict__ u,
                                               const float* __restrict__ Dv,
                                               float* __restrict__ y) {
    extern __shared__ char smem[];
    char* pAh = smem;
    char* pAl = smem + 16384;
    char* pBh = smem + 32768;
    char* pBl = smem + 49152;
    int tid = threadIdx.x;
    int lane = tid & 31, g = lane >> 2, tig = lane & 3;
    int w = tid >> 5, wm = w >> 1, wn = w & 1;
    int n0 = blockIdx.x * 128;
    int m0 = blockIdx.y * 128;

    // stage A = preconverted X bf16 hi/lo (pure copies)
    #pragma unroll
    for (int i = 0; i < 4; ++i) {
        int task = tid + 256 * i;
        int row = task >> 3, kp = task & 7;
        size_t goff = ((size_t)(m0 + row) * N2 + kp * 8) * 2;
        int off = kp * 2048 + ((row ^ kp) << 4);
        *(uint4*)(pAh + off) = *(const uint4*)((const char*)g_Xh + goff);
        *(uint4*)(pAl + off) = *(const uint4*)((const char*)g_Xl + goff);
    }
    // stage B = W2 rows n0..n0+127 (128-row panels, psz 2048)
    #pragma unroll
    for (int i = 0; i < 4; ++i) {
        int task = tid + 256 * i;
        int n = task >> 3, kp = task & 7;
        size_t goff = ((size_t)(n0 + n) * N2 + kp * 8) * 2;
        int off = kp * 2048 + ((n ^ kp) << 4);
        *(uint4*)(pBh + off) = *(const uint4*)((const char*)g_W2h + goff);
        *(uint4*)(pBl + off) = *(const uint4*)((const char*)g_W2l + goff);
    }
    __syncthreads();

    float acc[2][8][4];
    #pragma unroll
    for (int mt = 0; mt < 2; ++mt)
        #pragma unroll
        for (int f = 0; f < 8; ++f)
            #pragma unroll
            for (int i = 0; i < 4; ++i) acc[mt][f][i] = 0.f;

    uint32_t aBh = smem_u32(pBh), aBl = smem_u32(pBl);
    uint32_t aAh = smem_u32(pAh), aAl = smem_u32(pAl);

    #pragma unroll
    for (int ks = 0; ks < 4; ++ks) {
        int p = ks * 2;
        uint32_t ah0[4], ah1[4], al0[4], al1[4];
        ldsm4(aAh + lmoff(p, wm * 32,      lane, 2048), ah0);
        ldsm4(aAh + lmoff(p, wm * 32 + 16, lane, 2048), ah1);
        ldsm4(aAl + lmoff(p, wm * 32,      lane, 2048), al0);
        ldsm4(aAl + lmoff(p, wm * 32 + 16, lane, 2048), al1);
        uint32_t bh[16], bl[16];
        #pragma unroll
        for (int s = 0; s < 4; ++s) {
            ldsm4(aBh + lmoff(p, wn * 64 + s * 16, lane, 2048), bh + 4 * s);
            ldsm4(aBl + lmoff(p, wn * 64 + s * 16, lane, 2048), bl + 4 * s);
        }
        #pragma unroll
        for (int f = 0; f < 8; ++f) {
            int q = (f >> 1) * 4 + (f & 1);
            uint32_t bfh[2] = { bh[q], bh[q + 2] };
            uint32_t bfl[2] = { bl[q], bl[q + 2] };
            mma16816(acc[0][f], ah0, bfh);
            mma16816(acc[0][f], ah0, bfl);
            mma16816(acc[0][f], al0, bfh);
            mma16816(acc[1][f], ah1, bfh);
            mma16816(acc[1][f], ah1, bfl);
            mma16816(acc[1][f], al1, bfh);
        }
    }

    // epilogue: y = acc + D*u
    #pragma unroll
    for (int f = 0; f < 8; ++f) {
        int col = n0 + wn * 64 + f * 8 + 2 * tig;
        float2 dv = *(const float2*)(Dv + col);
        #pragma unroll
        for (int mt = 0; mt < 2; ++mt) {
            int r0 = m0 + wm * 32 + mt * 16 + g;
            float* a = acc[mt][f];
            size_t o0 = (size_t)r0 * DMODEL + col;
            size_t o1 = o0 + (size_t)8 * DMODEL;
            float2 u0 = *(const float2*)(u + o0);
            float2 u1 = *(const float2*)(u + o1);
            *(float2*)(y + o0) = make_float2(a[0] + dv.x * u0.x, a[1] + dv.y * u0.y);
            *(float2*)(y + o1) = make_float2(a[2] + dv.x * u1.x, a[3] + dv.y * u1.y);
        }
    }
}

// ---------------- launch ----------------
extern "C" void kernel_launch(void* const* d_in, const int* in_sizes, int n_in,
                              void* d_out, int out_size) {
    const float* u    = (const float*)d_in[0];
    const float* Lur  = (const float*)d_in[1];
    const float* Lim  = (const float*)d_in[2];
    const float* Bre  = (const float*)d_in[3];
    const float* Bim  = (const float*)d_in[4];
    const float* Cre  = (const float*)d_in[5];
    const float* Cim  = (const float*)d_in[6];
    const float* Dv   = (const float*)d_in[7];
    const float* logD = (const float*)d_in[8];
    float* y = (float*)d_out;

    const int g1_bytes = 2 * G1_STAGE;   // 98304
    const int g2_bytes = 65536;
    cudaFuncSetAttribute(k_gemm1, cudaFuncAttributeMaxDynamicSharedMemorySize,
                         g1_bytes);
    cudaFuncSetAttribute(k_gemm2, cudaFuncAttributeMaxDynamicSharedMemorySize,
                         g2_bytes);

    k_params<<<1, 32>>>(Lur, Lim, logD);
    k_w1<<<128, 256>>>(Bre, Bim);
    k_w2<<<128, 256>>>(Cre, Cim);
    k_gemm1<<<MTOT / 128, 256, g1_bytes>>>(u);
    k_scan_local<<<(BATCH * NCHUNK) / 4, 128>>>();
    k_scan_prefix<<<1, BATCH * 32>>>();
    k_scan_fix<<<(BATCH * NCHUNK) / 4, 128>>>();
    k_gemm2<<<dim3(DMODEL / 128, MTOT / 128), 256, g2_bytes>>>(u, Dv, y);
}